// round 2
// baseline (speedup 1.0000x reference)
#include <cuda_runtime.h>
#include <cuda_bf16.h>
#include <cstdint>

// ---------------------------------------------------------------------------
// TargetTokenEncoder: hist/stats -> MLP(14->256, exact GELU) -> GEMM(256x256)
// Stage C via warp-level HMMA (mma.sync m16n8k16 bf16, fp32 accum),
// bf16x3 split precision: Ah*Bh + Ah*Bl + Al*Bh (rel err ~2^-17).
// NOTE: toolchain emits compute_103 (no 'a') PTX -> tcgen05 unavailable.
// ---------------------------------------------------------------------------

static constexpr int S      = 128;
static constexpr int TD     = 256;
static constexpr int TILE_M = 128;

// strides chosen for conflict-free ldmatrix (row stride mod 128B = 16B)
static constexpr int A_STRIDE = 528;              // 256 bf16 + 8 pad
static constexpr int B_STRIDE = 272;              // 128 bf16 + 8 pad

static constexpr int OFF_A_HI  = 0;               // 128 x 528  = 67584
static constexpr int OFF_A_LO  = 67584;
static constexpr int OFF_B_HI  = 135168;          // 128 x 272  = 34816
static constexpr int OFF_B_LO  = 169984;
static constexpr int OFF_STATS = 204800;          // 128 x 16 f32 = 8192
static constexpr int OFF_B2    = 212992;          // 256 f32 = 1024
static constexpr int SMEM_BYTES = 214016;

static constexpr int D_A_LO = OFF_A_LO - OFF_A_HI;   // 67584
static constexpr int D_B_LO = OFF_B_LO - OFF_B_HI;   // 34816

__device__ __forceinline__ uint32_t smem_u32(const void* p) {
    uint32_t a;
    asm("{ .reg .u64 t; cvta.to.shared.u64 t, %1; cvt.u32.u64 %0, t; }" : "=r"(a) : "l"(p));
    return a;
}

__device__ __forceinline__ void ldm4(uint32_t* r, uint32_t addr) {
    asm volatile("ldmatrix.sync.aligned.m8n8.x4.shared.b16 {%0,%1,%2,%3}, [%4];"
                 : "=r"(r[0]), "=r"(r[1]), "=r"(r[2]), "=r"(r[3]) : "r"(addr));
}

__device__ __forceinline__ void mma_bf16(float* c, const uint32_t* a,
                                         uint32_t b0, uint32_t b1) {
    asm volatile("mma.sync.aligned.m16n8k16.row.col.f32.bf16.bf16.f32 "
                 "{%0,%1,%2,%3}, {%4,%5,%6,%7}, {%8,%9}, {%0,%1,%2,%3};"
                 : "+f"(c[0]), "+f"(c[1]), "+f"(c[2]), "+f"(c[3])
                 : "r"(a[0]), "r"(a[1]), "r"(a[2]), "r"(a[3]), "r"(b0), "r"(b1));
}

__device__ __forceinline__ void store_split(char* hi_b, char* lo_b,
                                            uint32_t off, float v) {
    __nv_bfloat16 hi = __float2bfloat16(v);
    float rem = v - __bfloat162float(hi);
    __nv_bfloat16 lo = __float2bfloat16(rem);
    *reinterpret_cast<__nv_bfloat16*>(hi_b + off) = hi;
    *reinterpret_cast<__nv_bfloat16*>(lo_b + off) = lo;
}

__global__ __launch_bounds__(256, 1)
void tte_kernel(const int* __restrict__ y, const float* __restrict__ w1,
                const float* __restrict__ b1, const float* __restrict__ w2,
                const float* __restrict__ b2, float* __restrict__ out)
{
    extern __shared__ char smem[];
    const uint32_t sb = smem_u32(smem);
    const int tid = threadIdx.x;
    const int wid = tid >> 5;
    const int lid = tid & 31;

    float* stats = reinterpret_cast<float*>(smem + OFF_STATS);
    float* b2s   = reinterpret_cast<float*>(smem + OFF_B2);

    // ---------------- Phase 1: warps 0-3 histogram+stats ; warps 4-7 b2
    if (tid < TILE_M) {
        const int4* p = reinterpret_cast<const int4*>(
            y + ((size_t)blockIdx.x * TILE_M + tid) * S);
        uint32_t a0 = 0, a1 = 0, a2 = 0;   // 4x8-bit packed counters
        #pragma unroll
        for (int i = 0; i < S / 4; i++) {
            int4 v = __ldg(p + i);
            { int x = v.x; uint32_t b = 1u << ((x & 3) << 3);
              if (x < 4) a0 += b; else if (x < 8) a1 += b; else a2 += b; }
            { int x = v.y; uint32_t b = 1u << ((x & 3) << 3);
              if (x < 4) a0 += b; else if (x < 8) a1 += b; else a2 += b; }
            { int x = v.z; uint32_t b = 1u << ((x & 3) << 3);
              if (x < 4) a0 += b; else if (x < 8) a1 += b; else a2 += b; }
            { int x = v.w; uint32_t b = 1u << ((x & 3) << 3);
              if (x < 4) a0 += b; else if (x < 8) a1 += b; else a2 += b; }
        }
        int cnt[10];
        float pr[10];
        #pragma unroll
        for (int c = 0; c < 10; c++) {
            uint32_t a = (c < 4) ? a0 : ((c < 8) ? a1 : a2);
            cnt[c] = (int)((a >> ((c & 3) * 8)) & 0xFF);
            pr[c]  = (float)cnt[c] * (1.0f / 128.0f);   // exact in fp32
        }
        float ent = 0.0f, pm = 0.0f, nnz = 0.0f;
        #pragma unroll
        for (int c = 0; c < 10; c++) {
            ent -= pr[c] * logf(pr[c] + 1e-6f);         // p==0 -> exactly 0
            pm   = fmaxf(pm, pr[c]);
            nnz += (cnt[c] > 0) ? 1.0f : 0.0f;
        }
        float* sr = stats + tid * 16;
        #pragma unroll
        for (int c = 0; c < 10; c++) sr[c] = pr[c];
        sr[10] = nnz; sr[11] = ent; sr[12] = 128.0f; sr[13] = pm;
        sr[14] = 0.0f; sr[15] = 0.0f;
    } else {
        int u = tid - 128;
        b2s[u] = __ldg(b2 + u);
        b2s[u + 128] = __ldg(b2 + u + 128);
    }
    __syncthreads();

    // ---------------- Phase 2: stage-B MLP. thread t owns h column n=t.
    {
        float wv[14];
        #pragma unroll
        for (int k = 0; k < 14; k++) wv[k] = __ldg(w1 + k * TD + tid);
        const float bb = __ldg(b1 + tid);
        for (int r = 0; r < TILE_M; r++) {
            const float4* sp = reinterpret_cast<const float4*>(stats + r * 16);
            float4 s0 = sp[0], s1 = sp[1], s2 = sp[2], s3 = sp[3];
            float x = bb;
            x = fmaf(s0.x, wv[0], x);  x = fmaf(s0.y, wv[1], x);
            x = fmaf(s0.z, wv[2], x);  x = fmaf(s0.w, wv[3], x);
            x = fmaf(s1.x, wv[4], x);  x = fmaf(s1.y, wv[5], x);
            x = fmaf(s1.z, wv[6], x);  x = fmaf(s1.w, wv[7], x);
            x = fmaf(s2.x, wv[8], x);  x = fmaf(s2.y, wv[9], x);
            x = fmaf(s2.z, wv[10], x); x = fmaf(s2.w, wv[11], x);
            x = fmaf(s3.x, wv[12], x); x = fmaf(s3.y, wv[13], x);
            float g = 0.5f * x * (1.0f + erff(x * 0.707106781186547524f));
            store_split(smem + OFF_A_HI, smem + OFF_A_LO,
                        (uint32_t)(r * A_STRIDE + tid * 2), g);
        }
    }

    // ---------------- Phase 3: GEMM h[128,256] @ w2[256,256], bf16x3 HMMA
    const int wm = wid >> 1;           // 0..3 -> M offset 32*wm
    const int wn = wid & 1;            // 0..1 -> N offset 64*wn
    const int mo = wm * 32;
    const int j8 = lid >> 3;           // which 8x8 matrix this lane addresses
    const int lr = lid & 7;

    // ldmatrix base offsets (hi buffers); lo = +D_A_LO / +D_B_LO
    uint32_t aoff[2], boff[4];
    #pragma unroll
    for (int i = 0; i < 2; i++)
        aoff[i] = sb + OFF_A_HI
                + (uint32_t)((mo + i * 16 + ((j8 & 1) << 3) + lr) * A_STRIDE)
                + (uint32_t)((j8 >> 1) << 4);
    #pragma unroll
    for (int p = 0; p < 4; p++)
        boff[p] = sb + OFF_B_HI
                + (uint32_t)((wn * 64 + p * 16 + ((j8 >> 1) << 3) + lr) * B_STRIDE)
                + (uint32_t)((j8 & 1) << 4);

    const int g  = lid >> 2;           // c-frag row within tile
    const int tg = lid & 3;            // c-frag col pair

    #pragma unroll 1
    for (int nc = 0; nc < 2; nc++) {
        float acc[2][8][4];
        #pragma unroll
        for (int i = 0; i < 2; i++)
            #pragma unroll
            for (int j = 0; j < 8; j++)
                #pragma unroll
                for (int q = 0; q < 4; q++) acc[i][j][q] = 0.0f;

        #pragma unroll 1
        for (int kc = 0; kc < 2; kc++) {
            __syncthreads();   // prior MMA pass done reading B before refill
            // fill B chunk: B[nl][kl] = w2[kc*128+kl][nc*128+nl], split bf16
            #pragma unroll 4
            for (int it = 0; it < 64; it++) {
                int idx = tid + it * 256;
                int nl = idx & 127;
                int kl = idx >> 7;
                float w = __ldg(w2 + (size_t)(kc * 128 + kl) * TD + nc * 128 + nl);
                store_split(smem + OFF_B_HI, smem + OFF_B_LO,
                            (uint32_t)(nl * B_STRIDE + kl * 2), w);
            }
            __syncthreads();

            #pragma unroll
            for (int ks = 0; ks < 8; ks++) {
                uint32_t aH[2][4], aL[2][4], bH[4][4], bL[4][4];
                const uint32_t ka = (uint32_t)(kc * 256 + ks * 32); // A col bytes
                const uint32_t kb = (uint32_t)(ks * 32);            // B col bytes
                ldm4(aH[0], aoff[0] + ka);
                ldm4(aH[1], aoff[1] + ka);
                ldm4(aL[0], aoff[0] + ka + D_A_LO);
                ldm4(aL[1], aoff[1] + ka + D_A_LO);
                #pragma unroll
                for (int p = 0; p < 4; p++) {
                    ldm4(bH[p], boff[p] + kb);
                    ldm4(bL[p], boff[p] + kb + D_B_LO);
                }
                #pragma unroll
                for (int i = 0; i < 2; i++) {
                    #pragma unroll
                    for (int j = 0; j < 8; j++) {
                        const int p = j >> 1, h = (j & 1) * 2;
                        mma_bf16(acc[i][j], aH[i], bH[p][h], bH[p][h + 1]); // Ah*Bh
                        mma_bf16(acc[i][j], aH[i], bL[p][h], bL[p][h + 1]); // Ah*Bl
                        mma_bf16(acc[i][j], aL[i], bH[p][h], bH[p][h + 1]); // Al*Bh
                    }
                }
            }
        }

        // epilogue for this N-chunk
        const size_t rbase = (size_t)blockIdx.x * TILE_M;
        #pragma unroll
        for (int i = 0; i < 2; i++) {
            #pragma unroll
            for (int j = 0; j < 8; j++) {
                const int col = nc * 128 + wn * 64 + j * 8 + tg * 2;
                const float bb0 = b2s[col], bb1 = b2s[col + 1];
                const size_t r0 = rbase + mo + i * 16 + g;
                float2 v0 = make_float2(acc[i][j][0] + bb0, acc[i][j][1] + bb1);
                float2 v1 = make_float2(acc[i][j][2] + bb0, acc[i][j][3] + bb1);
                *reinterpret_cast<float2*>(out + r0 * TD + col) = v0;
                *reinterpret_cast<float2*>(out + (r0 + 8) * TD + col) = v1;
            }
        }
    }
}

extern "C" void kernel_launch(void* const* d_in, const int* in_sizes, int n_in,
                              void* d_out, int out_size) {
    const int*   y  = (const int*)d_in[0];
    const float* w1 = (const float*)d_in[1];
    const float* b1 = (const float*)d_in[2];
    const float* w2 = (const float*)d_in[3];
    const float* b2 = (const float*)d_in[4];
    float* out = (float*)d_out;
    const int Btot = in_sizes[0] / S;          // 65536 rows
    const int grid = Btot / TILE_M;            // 512 CTAs

    cudaFuncSetAttribute(tte_kernel, cudaFuncAttributeMaxDynamicSharedMemorySize,
                         SMEM_BYTES);
    tte_kernel<<<grid, 256, SMEM_BYTES>>>(y, w1, b1, w2, b2, out);
}

// round 3
// speedup vs baseline: 1.1208x; 1.1208x over previous
#include <cuda_runtime.h>
#include <cuda_bf16.h>
#include <cstdint>

// ---------------------------------------------------------------------------
// TargetTokenEncoder: hist/stats -> MLP(14->256, exact GELU) -> GEMM(256x256)
// Stage C via warp-level HMMA (mma.sync m16n8k16 bf16, fp32 accum),
// bf16x3 split precision: Ah*Bh + Ah*Bl + Al*Bh (rel err ~5e-6).
// R3: TILE_M=64, smem 113.7KB -> 2 CTAs/SM so phases overlap across CTAs.
// ---------------------------------------------------------------------------

static constexpr int S      = 128;
static constexpr int TD     = 256;
static constexpr int TILE_M = 64;

// row strides chosen for conflict-free ldmatrix (stride/16 odd -> bank rotate)
static constexpr int A_STRIDE = 528;              // 256 bf16 + 8 pad
static constexpr int B_STRIDE = 80;               // 32 bf16 + 8 pad

static constexpr int OFF_A_HI  = 0;               // 64 x 528  = 33792
static constexpr int OFF_A_LO  = 33792;
static constexpr int OFF_B_HI  = 67584;           // 256 x 80  = 20480
static constexpr int OFF_B_LO  = 88064;
static constexpr int OFF_STATS = 108544;          // 64 x 16 f32 = 4096
static constexpr int OFF_B2    = 112640;          // 256 f32 = 1024
static constexpr int SMEM_BYTES = 113664;

static constexpr int D_A_LO = OFF_A_LO - OFF_A_HI;   // 33792
static constexpr int D_B_LO = OFF_B_LO - OFF_B_HI;   // 20480

__device__ __forceinline__ uint32_t smem_u32(const void* p) {
    uint32_t a;
    asm("{ .reg .u64 t; cvta.to.shared.u64 t, %1; cvt.u32.u64 %0, t; }" : "=r"(a) : "l"(p));
    return a;
}

__device__ __forceinline__ void ldm4(uint32_t* r, uint32_t addr) {
    asm volatile("ldmatrix.sync.aligned.m8n8.x4.shared.b16 {%0,%1,%2,%3}, [%4];"
                 : "=r"(r[0]), "=r"(r[1]), "=r"(r[2]), "=r"(r[3]) : "r"(addr));
}

__device__ __forceinline__ void mma_bf16(float* c, const uint32_t* a,
                                         uint32_t b0, uint32_t b1) {
    asm volatile("mma.sync.aligned.m16n8k16.row.col.f32.bf16.bf16.f32 "
                 "{%0,%1,%2,%3}, {%4,%5,%6,%7}, {%8,%9}, {%0,%1,%2,%3};"
                 : "+f"(c[0]), "+f"(c[1]), "+f"(c[2]), "+f"(c[3])
                 : "r"(a[0]), "r"(a[1]), "r"(a[2]), "r"(a[3]), "r"(b0), "r"(b1));
}

__device__ __forceinline__ void store_split(char* hi_b, char* lo_b,
                                            uint32_t off, float v) {
    __nv_bfloat16 hi = __float2bfloat16(v);
    float rem = v - __bfloat162float(hi);
    __nv_bfloat16 lo = __float2bfloat16(rem);
    *reinterpret_cast<__nv_bfloat16*>(hi_b + off) = hi;
    *reinterpret_cast<__nv_bfloat16*>(lo_b + off) = lo;
}

// fill B chunk for k-block kc: B[nl][kl] = w2[kc*32+kl][nl], split bf16
__device__ __forceinline__ void fill_b(char* smem, const float* __restrict__ w2,
                                       int kc, int tid0, int nthreads) {
    for (int idx = tid0; idx < 256 * 32; idx += nthreads) {
        int nl = idx & 255;
        int kl = idx >> 8;
        float w = __ldg(w2 + (size_t)(kc * 32 + kl) * TD + nl);
        store_split(smem + OFF_B_HI, smem + OFF_B_LO,
                    (uint32_t)(nl * B_STRIDE + kl * 2), w);
    }
}

__global__ __launch_bounds__(256, 2)
void tte_kernel(const int* __restrict__ y, const float* __restrict__ w1,
                const float* __restrict__ b1, const float* __restrict__ w2,
                const float* __restrict__ b2, float* __restrict__ out)
{
    extern __shared__ char smem[];
    const uint32_t sb = smem_u32(smem);
    const int tid = threadIdx.x;
    const int wid = tid >> 5;
    const int lid = tid & 31;

    float* stats = reinterpret_cast<float*>(smem + OFF_STATS);
    float* b2s   = reinterpret_cast<float*>(smem + OFF_B2);

    // ---------------- Phase 1: threads 0-63 histogram+stats for 64 rows;
    //                  threads 64-255 prefetch b2 + fill B chunk kc=0
    if (tid < TILE_M) {
        const int4* p = reinterpret_cast<const int4*>(
            y + ((size_t)blockIdx.x * TILE_M + tid) * S);
        uint32_t a0 = 0, a1 = 0, a2 = 0;   // 4x8-bit packed counters
        #pragma unroll
        for (int i = 0; i < S / 4; i++) {
            int4 v = __ldg(p + i);
            { int x = v.x; uint32_t b = 1u << ((x & 3) << 3);
              if (x < 4) a0 += b; else if (x < 8) a1 += b; else a2 += b; }
            { int x = v.y; uint32_t b = 1u << ((x & 3) << 3);
              if (x < 4) a0 += b; else if (x < 8) a1 += b; else a2 += b; }
            { int x = v.z; uint32_t b = 1u << ((x & 3) << 3);
              if (x < 4) a0 += b; else if (x < 8) a1 += b; else a2 += b; }
            { int x = v.w; uint32_t b = 1u << ((x & 3) << 3);
              if (x < 4) a0 += b; else if (x < 8) a1 += b; else a2 += b; }
        }
        int cnt[10];
        float pr[10];
        #pragma unroll
        for (int c = 0; c < 10; c++) {
            uint32_t a = (c < 4) ? a0 : ((c < 8) ? a1 : a2);
            cnt[c] = (int)((a >> ((c & 3) * 8)) & 0xFF);
            pr[c]  = (float)cnt[c] * (1.0f / 128.0f);   // exact in fp32
        }
        float ent = 0.0f, pm = 0.0f, nnz = 0.0f;
        #pragma unroll
        for (int c = 0; c < 10; c++) {
            ent -= pr[c] * logf(pr[c] + 1e-6f);         // p==0 -> exactly 0
            pm   = fmaxf(pm, pr[c]);
            nnz += (cnt[c] > 0) ? 1.0f : 0.0f;
        }
        float* sr = stats + tid * 16;
        #pragma unroll
        for (int c = 0; c < 10; c++) sr[c] = pr[c];
        sr[10] = nnz; sr[11] = ent; sr[12] = 128.0f; sr[13] = pm;
        sr[14] = 0.0f; sr[15] = 0.0f;
    } else {
        for (int u = tid - 64; u < 256; u += 192) b2s[u] = __ldg(b2 + u);
        fill_b(smem, w2, 0, tid - 64, 192);
    }
    __syncthreads();

    // ---------------- Phase 2: stage-B MLP. thread t owns h column n=t.
    {
        float wv[14];
        #pragma unroll
        for (int k = 0; k < 14; k++) wv[k] = __ldg(w1 + k * TD + tid);
        const float bb = __ldg(b1 + tid);
        for (int r = 0; r < TILE_M; r++) {
            const float4* sp = reinterpret_cast<const float4*>(stats + r * 16);
            float4 s0 = sp[0], s1 = sp[1], s2 = sp[2], s3 = sp[3];
            float x = bb;
            x = fmaf(s0.x, wv[0], x);  x = fmaf(s0.y, wv[1], x);
            x = fmaf(s0.z, wv[2], x);  x = fmaf(s0.w, wv[3], x);
            x = fmaf(s1.x, wv[4], x);  x = fmaf(s1.y, wv[5], x);
            x = fmaf(s1.z, wv[6], x);  x = fmaf(s1.w, wv[7], x);
            x = fmaf(s2.x, wv[8], x);  x = fmaf(s2.y, wv[9], x);
            x = fmaf(s2.z, wv[10], x); x = fmaf(s2.w, wv[11], x);
            x = fmaf(s3.x, wv[12], x); x = fmaf(s3.y, wv[13], x);
            float g = 0.5f * x * (1.0f + erff(x * 0.707106781186547524f));
            store_split(smem + OFF_A_HI, smem + OFF_A_LO,
                        (uint32_t)(r * A_STRIDE + tid * 2), g);
        }
    }
    __syncthreads();

    // ---------------- Phase 3: GEMM h[64,256] @ w2[256,256], bf16x3 HMMA
    // 8 warps = 2 (M, 32 rows each) x 4 (N, 64 cols each)
    const int wm = wid >> 2;           // 0..1
    const int wn = wid & 3;            // 0..3
    const int mo = wm * 32;
    const int j8 = lid >> 3;           // which 8x8 matrix this lane addresses
    const int lr = lid & 7;

    uint32_t aoff[2], boff[4];
    #pragma unroll
    for (int i = 0; i < 2; i++)
        aoff[i] = sb + OFF_A_HI
                + (uint32_t)((mo + i * 16 + ((j8 & 1) << 3) + lr) * A_STRIDE)
                + (uint32_t)((j8 >> 1) << 4);
    #pragma unroll
    for (int p = 0; p < 4; p++)
        boff[p] = sb + OFF_B_HI
                + (uint32_t)((wn * 64 + p * 16 + ((j8 >> 1) << 3) + lr) * B_STRIDE)
                + (uint32_t)((j8 & 1) << 4);

    float acc[2][8][4];
    #pragma unroll
    for (int i = 0; i < 2; i++)
        #pragma unroll
        for (int j = 0; j < 8; j++)
            #pragma unroll
            for (int q = 0; q < 4; q++) acc[i][j][q] = 0.0f;

    #pragma unroll 1
    for (int kc = 0; kc < 8; kc++) {
        if (kc > 0) {
            __syncthreads();               // prior reads of B done
            fill_b(smem, w2, kc, tid, 256);
            __syncthreads();
        }
        #pragma unroll
        for (int ks = 0; ks < 2; ks++) {
            const uint32_t ka = (uint32_t)(kc * 64 + ks * 32);  // A col bytes
            const uint32_t kb = (uint32_t)(ks * 32);            // B col bytes
            uint32_t aH[2][4], aL[2][4];
            ldm4(aH[0], aoff[0] + ka);
            ldm4(aH[1], aoff[1] + ka);
            ldm4(aL[0], aoff[0] + ka + D_A_LO);
            ldm4(aL[1], aoff[1] + ka + D_A_LO);
            #pragma unroll
            for (int p = 0; p < 4; p++) {
                uint32_t bH[4], bL[4];
                ldm4(bH, boff[p] + kb);
                ldm4(bL, boff[p] + kb + D_B_LO);
                #pragma unroll
                for (int i = 0; i < 2; i++) {
                    #pragma unroll
                    for (int jj = 0; jj < 2; jj++) {
                        const int j = p * 2 + jj, h = jj * 2;
                        mma_bf16(acc[i][j], aH[i], bH[h], bH[h + 1]); // Ah*Bh
                        mma_bf16(acc[i][j], aH[i], bL[h], bL[h + 1]); // Ah*Bl
                        mma_bf16(acc[i][j], aL[i], bH[h], bH[h + 1]); // Al*Bh
                    }
                }
            }
        }
    }

    // ---------------- Epilogue
    {
        const int g  = lid >> 2;           // c-frag row within tile
        const int tg = lid & 3;            // c-frag col pair
        const size_t rbase = (size_t)blockIdx.x * TILE_M;
        #pragma unroll
        for (int i = 0; i < 2; i++) {
            #pragma unroll
            for (int j = 0; j < 8; j++) {
                const int col = wn * 64 + j * 8 + tg * 2;
                const float bb0 = b2s[col], bb1 = b2s[col + 1];
                const size_t r0 = rbase + mo + i * 16 + g;
                float2 v0 = make_float2(acc[i][j][0] + bb0, acc[i][j][1] + bb1);
                float2 v1 = make_float2(acc[i][j][2] + bb0, acc[i][j][3] + bb1);
                *reinterpret_cast<float2*>(out + r0 * TD + col) = v0;
                *reinterpret_cast<float2*>(out + (r0 + 8) * TD + col) = v1;
            }
        }
    }
}

extern "C" void kernel_launch(void* const* d_in, const int* in_sizes, int n_in,
                              void* d_out, int out_size) {
    const int*   y  = (const int*)d_in[0];
    const float* w1 = (const float*)d_in[1];
    const float* b1 = (const float*)d_in[2];
    const float* w2 = (const float*)d_in[3];
    const float* b2 = (const float*)d_in[4];
    float* out = (float*)d_out;
    const int Btot = in_sizes[0] / S;          // 65536 rows
    const int grid = Btot / TILE_M;            // 1024 CTAs

    cudaFuncSetAttribute(tte_kernel, cudaFuncAttributeMaxDynamicSharedMemorySize,
                         SMEM_BYTES);
    tte_kernel<<<grid, 256, SMEM_BYTES>>>(y, w1, b1, w2, b2, out);
}

// round 4
// speedup vs baseline: 1.7066x; 1.5226x over previous
#include <cuda_runtime.h>
#include <cuda_bf16.h>
#include <cstdint>

// ---------------------------------------------------------------------------
// TargetTokenEncoder: hist/stats -> MLP(14->256, exact GELU) -> GEMM(256x256)
// Stage C via warp-level HMMA (mma.sync m16n8k16 bf16, fp32 accum),
// bf16x3 split precision: Ah*Bh + Ah*Bl + Al*Bh (rel err ~5e-6).
// R4: w2 pre-split into bf16 hi/lo scratch (smem byte-image layout) by a prep
//     kernel; per-kc B fill becomes a cp.async 16B-vector copy.
// ---------------------------------------------------------------------------

static constexpr int S      = 128;
static constexpr int TD     = 256;
static constexpr int TILE_M = 64;

// row strides chosen for conflict-free ldmatrix (stride/16 odd -> bank rotate)
static constexpr int A_STRIDE = 528;              // 256 bf16 + 8 pad
static constexpr int B_STRIDE = 80;               // 32 bf16 + 8 pad
static constexpr int B_CHUNK_BYTES = 256 * B_STRIDE;   // 20480
static constexpr int N_KC = 8;                    // 8 k-chunks of 32

static constexpr int OFF_A_HI  = 0;               // 64 x 528  = 33792
static constexpr int OFF_A_LO  = 33792;
static constexpr int OFF_B_HI  = 67584;           // 256 x 80  = 20480
static constexpr int OFF_B_LO  = 88064;
static constexpr int OFF_STATS = 108544;          // 64 x 16 f32 = 4096
static constexpr int OFF_B2    = 112640;          // 256 f32 = 1024
static constexpr int SMEM_BYTES = 113664;

static constexpr int D_A_LO = OFF_A_LO - OFF_A_HI;   // 33792
static constexpr int D_B_LO = OFF_B_LO - OFF_B_HI;   // 20480

// persistent scratch: w2 split-bf16, exact smem B-chunk byte image per kc
__device__ __align__(16) __nv_bfloat16 g_b_hi[N_KC * 256 * (B_STRIDE / 2)];
__device__ __align__(16) __nv_bfloat16 g_b_lo[N_KC * 256 * (B_STRIDE / 2)];

__device__ __forceinline__ uint32_t smem_u32(const void* p) {
    uint32_t a;
    asm("{ .reg .u64 t; cvta.to.shared.u64 t, %1; cvt.u32.u64 %0, t; }" : "=r"(a) : "l"(p));
    return a;
}

__device__ __forceinline__ void cp16(uint32_t saddr, const void* gptr) {
    asm volatile("cp.async.cg.shared.global [%0], [%1], 16;"
                 :: "r"(saddr), "l"(gptr) : "memory");
}

__device__ __forceinline__ void ldm4(uint32_t* r, uint32_t addr) {
    asm volatile("ldmatrix.sync.aligned.m8n8.x4.shared.b16 {%0,%1,%2,%3}, [%4];"
                 : "=r"(r[0]), "=r"(r[1]), "=r"(r[2]), "=r"(r[3]) : "r"(addr));
}

__device__ __forceinline__ void mma_bf16(float* c, const uint32_t* a,
                                         uint32_t b0, uint32_t b1) {
    asm volatile("mma.sync.aligned.m16n8k16.row.col.f32.bf16.bf16.f32 "
                 "{%0,%1,%2,%3}, {%4,%5,%6,%7}, {%8,%9}, {%0,%1,%2,%3};"
                 : "+f"(c[0]), "+f"(c[1]), "+f"(c[2]), "+f"(c[3])
                 : "r"(a[0]), "r"(a[1]), "r"(a[2]), "r"(a[3]), "r"(b0), "r"(b1));
}

__device__ __forceinline__ void store_split(char* hi_b, char* lo_b,
                                            uint32_t off, float v) {
    __nv_bfloat16 hi = __float2bfloat16(v);
    float rem = v - __bfloat162float(hi);
    __nv_bfloat16 lo = __float2bfloat16(rem);
    *reinterpret_cast<__nv_bfloat16*>(hi_b + off) = hi;
    *reinterpret_cast<__nv_bfloat16*>(lo_b + off) = lo;
}

// ---------------- prep kernel: split w2 into chunked smem-image layout
__global__ __launch_bounds__(256)
void prep_kernel(const float* __restrict__ w2) {
    int idx = blockIdx.x * 256 + threadIdx.x;        // 0 .. 81920
    const int total = N_KC * 256 * (B_STRIDE / 2);
    if (idx >= total) return;
    int kc  = idx / (256 * 40);
    int rem = idx % (256 * 40);
    int nl  = rem / 40;
    int j   = rem % 40;
    float v = (j < 32) ? __ldg(w2 + (size_t)(kc * 32 + j) * TD + nl) : 0.0f;
    __nv_bfloat16 hi = __float2bfloat16(v);
    float lo = v - __bfloat162float(hi);
    g_b_hi[idx] = hi;
    g_b_lo[idx] = __float2bfloat16(lo);
}

// copy one pre-split B chunk into smem via cp.async (16B granules)
__device__ __forceinline__ void fill_b_copy(uint32_t sb, int kc,
                                            int tid0, int nthreads) {
    const char* shi = reinterpret_cast<const char*>(g_b_hi) + kc * B_CHUNK_BYTES;
    const char* slo = reinterpret_cast<const char*>(g_b_lo) + kc * B_CHUNK_BYTES;
    for (int i = tid0; i < B_CHUNK_BYTES / 16; i += nthreads) {
        cp16(sb + OFF_B_HI + i * 16, shi + i * 16);
        cp16(sb + OFF_B_LO + i * 16, slo + i * 16);
    }
    asm volatile("cp.async.commit_group;" ::: "memory");
}

__device__ __forceinline__ void cp_wait_all() {
    asm volatile("cp.async.wait_group 0;" ::: "memory");
}

__global__ __launch_bounds__(256, 2)
void tte_kernel(const int* __restrict__ y, const float* __restrict__ w1,
                const float* __restrict__ b1,
                const float* __restrict__ b2, float* __restrict__ out)
{
    extern __shared__ char smem[];
    const uint32_t sb = smem_u32(smem);
    const int tid = threadIdx.x;
    const int wid = tid >> 5;
    const int lid = tid & 31;

    float* stats = reinterpret_cast<float*>(smem + OFF_STATS);
    float* b2s   = reinterpret_cast<float*>(smem + OFF_B2);

    // ---------------- Phase 1: threads 0-63 histogram+stats for 64 rows;
    //                  threads 64-255 prefetch b2 + copy B chunk kc=0
    if (tid < TILE_M) {
        const int4* p = reinterpret_cast<const int4*>(
            y + ((size_t)blockIdx.x * TILE_M + tid) * S);
        uint32_t a0 = 0, a1 = 0, a2 = 0;   // 4x8-bit packed counters
        #pragma unroll
        for (int i = 0; i < S / 4; i++) {
            int4 v = __ldg(p + i);
            { int x = v.x; uint32_t b = 1u << ((x & 3) << 3);
              if (x < 4) a0 += b; else if (x < 8) a1 += b; else a2 += b; }
            { int x = v.y; uint32_t b = 1u << ((x & 3) << 3);
              if (x < 4) a0 += b; else if (x < 8) a1 += b; else a2 += b; }
            { int x = v.z; uint32_t b = 1u << ((x & 3) << 3);
              if (x < 4) a0 += b; else if (x < 8) a1 += b; else a2 += b; }
            { int x = v.w; uint32_t b = 1u << ((x & 3) << 3);
              if (x < 4) a0 += b; else if (x < 8) a1 += b; else a2 += b; }
        }
        int cnt[10];
        float pr[10];
        #pragma unroll
        for (int c = 0; c < 10; c++) {
            uint32_t a = (c < 4) ? a0 : ((c < 8) ? a1 : a2);
            cnt[c] = (int)((a >> ((c & 3) * 8)) & 0xFF);
            pr[c]  = (float)cnt[c] * (1.0f / 128.0f);   // exact in fp32
        }
        float ent = 0.0f, pm = 0.0f, nnz = 0.0f;
        #pragma unroll
        for (int c = 0; c < 10; c++) {
            ent -= pr[c] * logf(pr[c] + 1e-6f);         // p==0 -> exactly 0
            pm   = fmaxf(pm, pr[c]);
            nnz += (cnt[c] > 0) ? 1.0f : 0.0f;
        }
        float* sr = stats + tid * 16;
        #pragma unroll
        for (int c = 0; c < 10; c++) sr[c] = pr[c];
        sr[10] = nnz; sr[11] = ent; sr[12] = 128.0f; sr[13] = pm;
        sr[14] = 0.0f; sr[15] = 0.0f;
    } else {
        for (int u = tid - 64; u < 256; u += 192) b2s[u] = __ldg(b2 + u);
        fill_b_copy(sb, 0, tid - 64, 192);
        cp_wait_all();
    }
    __syncthreads();

    // ---------------- Phase 2: stage-B MLP. thread t owns h column n=t.
    {
        float wv[14];
        #pragma unroll
        for (int k = 0; k < 14; k++) wv[k] = __ldg(w1 + k * TD + tid);
        const float bb = __ldg(b1 + tid);
        for (int r = 0; r < TILE_M; r++) {
            const float4* sp = reinterpret_cast<const float4*>(stats + r * 16);
            float4 s0 = sp[0], s1 = sp[1], s2 = sp[2], s3 = sp[3];
            float x = bb;
            x = fmaf(s0.x, wv[0], x);  x = fmaf(s0.y, wv[1], x);
            x = fmaf(s0.z, wv[2], x);  x = fmaf(s0.w, wv[3], x);
            x = fmaf(s1.x, wv[4], x);  x = fmaf(s1.y, wv[5], x);
            x = fmaf(s1.z, wv[6], x);  x = fmaf(s1.w, wv[7], x);
            x = fmaf(s2.x, wv[8], x);  x = fmaf(s2.y, wv[9], x);
            x = fmaf(s2.z, wv[10], x); x = fmaf(s2.w, wv[11], x);
            x = fmaf(s3.x, wv[12], x); x = fmaf(s3.y, wv[13], x);
            float g = 0.5f * x * (1.0f + erff(x * 0.707106781186547524f));
            store_split(smem + OFF_A_HI, smem + OFF_A_LO,
                        (uint32_t)(r * A_STRIDE + tid * 2), g);
        }
    }
    __syncthreads();

    // ---------------- Phase 3: GEMM h[64,256] @ w2[256,256], bf16x3 HMMA
    // 8 warps = 2 (M, 32 rows each) x 4 (N, 64 cols each)
    const int wm = wid >> 2;           // 0..1
    const int wn = wid & 3;            // 0..3
    const int mo = wm * 32;
    const int j8 = lid >> 3;           // which 8x8 matrix this lane addresses
    const int lr = lid & 7;

    uint32_t aoff[2], boff[4];
    #pragma unroll
    for (int i = 0; i < 2; i++)
        aoff[i] = sb + OFF_A_HI
                + (uint32_t)((mo + i * 16 + ((j8 & 1) << 3) + lr) * A_STRIDE)
                + (uint32_t)((j8 >> 1) << 4);
    #pragma unroll
    for (int p = 0; p < 4; p++)
        boff[p] = sb + OFF_B_HI
                + (uint32_t)((wn * 64 + p * 16 + ((j8 >> 1) << 3) + lr) * B_STRIDE)
                + (uint32_t)((j8 & 1) << 4);

    float acc[2][8][4];
    #pragma unroll
    for (int i = 0; i < 2; i++)
        #pragma unroll
        for (int j = 0; j < 8; j++)
            #pragma unroll
            for (int q = 0; q < 4; q++) acc[i][j][q] = 0.0f;

    #pragma unroll 1
    for (int kc = 0; kc < N_KC; kc++) {
        if (kc > 0) {
            __syncthreads();               // prior reads of B done
            fill_b_copy(sb, kc, tid, 256);
            cp_wait_all();
            __syncthreads();
        }
        #pragma unroll
        for (int ks = 0; ks < 2; ks++) {
            const uint32_t ka = (uint32_t)(kc * 64 + ks * 32);  // A col bytes
            const uint32_t kb = (uint32_t)(ks * 32);            // B col bytes
            uint32_t aH[2][4], aL[2][4];
            ldm4(aH[0], aoff[0] + ka);
            ldm4(aH[1], aoff[1] + ka);
            ldm4(aL[0], aoff[0] + ka + D_A_LO);
            ldm4(aL[1], aoff[1] + ka + D_A_LO);
            #pragma unroll
            for (int p = 0; p < 4; p++) {
                uint32_t bH[4], bL[4];
                ldm4(bH, boff[p] + kb);
                ldm4(bL, boff[p] + kb + D_B_LO);
                #pragma unroll
                for (int i = 0; i < 2; i++) {
                    #pragma unroll
                    for (int jj = 0; jj < 2; jj++) {
                        const int j = p * 2 + jj, h = jj * 2;
                        mma_bf16(acc[i][j], aH[i], bH[h], bH[h + 1]); // Ah*Bh
                        mma_bf16(acc[i][j], aH[i], bL[h], bL[h + 1]); // Ah*Bl
                        mma_bf16(acc[i][j], aL[i], bH[h], bH[h + 1]); // Al*Bh
                    }
                }
            }
        }
    }

    // ---------------- Epilogue
    {
        const int g  = lid >> 2;           // c-frag row within tile
        const int tg = lid & 3;            // c-frag col pair
        const size_t rbase = (size_t)blockIdx.x * TILE_M;
        #pragma unroll
        for (int i = 0; i < 2; i++) {
            #pragma unroll
            for (int j = 0; j < 8; j++) {
                const int col = wn * 64 + j * 8 + tg * 2;
                const float bb0 = b2s[col], bb1 = b2s[col + 1];
                const size_t r0 = rbase + mo + i * 16 + g;
                float2 v0 = make_float2(acc[i][j][0] + bb0, acc[i][j][1] + bb1);
                float2 v1 = make_float2(acc[i][j][2] + bb0, acc[i][j][3] + bb1);
                *reinterpret_cast<float2*>(out + r0 * TD + col) = v0;
                *reinterpret_cast<float2*>(out + (r0 + 8) * TD + col) = v1;
            }
        }
    }
}

extern "C" void kernel_launch(void* const* d_in, const int* in_sizes, int n_in,
                              void* d_out, int out_size) {
    const int*   y  = (const int*)d_in[0];
    const float* w1 = (const float*)d_in[1];
    const float* b1 = (const float*)d_in[2];
    const float* w2 = (const float*)d_in[3];
    const float* b2 = (const float*)d_in[4];
    float* out = (float*)d_out;
    const int Btot = in_sizes[0] / S;          // 65536 rows
    const int grid = Btot / TILE_M;            // 1024 CTAs

    // split w2 -> bf16 hi/lo scratch (smem image layout), then fused kernel
    prep_kernel<<<(N_KC * 256 * (B_STRIDE / 2) + 255) / 256, 256>>>(w2);

    cudaFuncSetAttribute(tte_kernel, cudaFuncAttributeMaxDynamicSharedMemorySize,
                         SMEM_BYTES);
    tte_kernel<<<grid, 256, SMEM_BYTES>>>(y, w1, b1, b2, out);
}